// round 3
// baseline (speedup 1.0000x reference)
#include <cuda_runtime.h>

#define N 4096
#define B 8
#define JT 128          // j per block == threads per block
#define ICH 128         // i per chunk
#define NCHUNK (N / ICH)   // 32
#define NJT (N / JT)       // 32

#define LOG2E 1.4426950408889634f
#define EXP_NEG1 0.36787944117144233f
// D = e - e^-1 ; fold 1/D^2 into the power scaling at the epilogue
#define DVAL 2.3504023872876028f
#define INV_D2 (1.0f / (DVAL * DVAL))
#define EPS 1e-5f

// -------- device scratch (no allocations allowed) --------
// i-side: {pos.x, pos.y, pos.z, outdirL.x}, {outdirL.y, outdirL.z, 0, 0}
__device__ float4 g_iside[N][2];
// j-side: {pos.x, pos.y, pos.z, indirL.x}, {indirL.y, indirL.z, 0, 0}
__device__ float4 g_jside[N][2];
// x transposed: xT[i] = {x[0][i]..x[7][i]} as 2 float4
__device__ float4 g_xT[N][2];
// partial sums: [chunk][j][b] as 2 float4
__device__ float4 g_part[NCHUNK][N][2];

// -------- prep: prescale directions by log2(e), transpose x --------
__global__ void prep_kernel(const float* __restrict__ x,
                            const float* __restrict__ pos,
                            const float* __restrict__ indir,
                            const float* __restrict__ outdir) {
    int i = blockIdx.x * blockDim.x + threadIdx.x;
    if (i >= N) return;
    float px = pos[i * 3 + 0], py = pos[i * 3 + 1], pz = pos[i * 3 + 2];
    float ox = outdir[i * 3 + 0] * LOG2E;
    float oy = outdir[i * 3 + 1] * LOG2E;
    float oz = outdir[i * 3 + 2] * LOG2E;
    float ix = indir[i * 3 + 0] * LOG2E;
    float iy = indir[i * 3 + 1] * LOG2E;
    float iz = indir[i * 3 + 2] * LOG2E;
    g_iside[i][0] = make_float4(px, py, pz, ox);
    g_iside[i][1] = make_float4(oy, oz, 0.f, 0.f);
    g_jside[i][0] = make_float4(px, py, pz, ix);
    g_jside[i][1] = make_float4(iy, iz, 0.f, 0.f);
    float4 a, b;
    a.x = x[0 * N + i]; a.y = x[1 * N + i]; a.z = x[2 * N + i]; a.w = x[3 * N + i];
    b.x = x[4 * N + i]; b.y = x[5 * N + i]; b.z = x[6 * N + i]; b.w = x[7 * N + i];
    g_xT[i][0] = a;
    g_xT[i][1] = b;
}

// -------- main: each thread owns one j, loops over an i-chunk --------
__global__ void __launch_bounds__(JT) main_kernel() {
    __shared__ float4 sI[ICH * 2];   // i-side geometry tile (4 KB)
    __shared__ float4 sX[ICH * 2];   // xT tile (4 KB)

    const int tid = threadIdx.x;
    const int j   = blockIdx.x * JT + tid;
    const int i0  = blockIdx.y * ICH;

    // cooperative stage of the i-chunk
    const float4* gI = &g_iside[i0][0];
    const float4* gX = &g_xT[i0][0];
    #pragma unroll
    for (int k = tid; k < ICH * 2; k += JT) {
        sI[k] = gI[k];
        sX[k] = gX[k];
    }

    // j-side registers
    float4 j0 = g_jside[j][0];
    float4 j1 = g_jside[j][1];
    const float pjx = j0.x, pjy = j0.y, pjz = j0.z;
    const float inx = j0.w, iny = j1.x, inz = j1.y;

    __syncthreads();

    // 8 batch accumulators as 4 packed f32x2 (bit pattern 0 == {0.f,0.f})
    unsigned long long acc0 = 0ull, acc1 = 0ull, acc2 = 0ull, acc3 = 0ull;

    #pragma unroll 8
    for (int i = 0; i < ICH; i++) {
        float4 A = sI[2 * i + 0];           // pos_i + odL.x
        float4 Bv = sI[2 * i + 1];          // odL.y, odL.z

        float dx = pjx - A.x;
        float dy = pjy - A.y;
        float dz = pjz - A.z;
        float d2 = fmaf(dx, dx, fmaf(dy, dy, dz * dz));
        float r;
        asm("rsqrt.approx.f32 %0, %1;" : "=f"(r) : "f"(fmaxf(d2, EPS)));

        // dots with log2e-prescaled directions
        float da = fmaf(dx, A.w, fmaf(dy, Bv.x, dz * Bv.y));   // delta . outdirL_i
        float db = fmaf(dx, inx, fmaf(dy, iny, dz * inz));     // delta . indirL_j

        float ea, eb;
        asm("ex2.approx.ftz.f32 %0, %1;" : "=f"(ea) : "f"(da * r));
        asm("ex2.approx.ftz.f32 %0, %1;" : "=f"(eb) : "f"(db * r));

        float g = (ea - EXP_NEG1) * (eb - EXP_NEG1);   // unnormalized gate

        unsigned long long gg;
        asm("mov.b64 %0, {%1, %1};" : "=l"(gg) : "f"(g));

        const ulonglong2* xp = reinterpret_cast<const ulonglong2*>(&sX[2 * i]);
        ulonglong2 Xa = xp[0];   // b0,b1 | b2,b3
        ulonglong2 Xb = xp[1];   // b4,b5 | b6,b7

        asm("fma.rn.f32x2 %0, %1, %2, %0;" : "+l"(acc0) : "l"(Xa.x), "l"(gg));
        asm("fma.rn.f32x2 %0, %1, %2, %0;" : "+l"(acc1) : "l"(Xa.y), "l"(gg));
        asm("fma.rn.f32x2 %0, %1, %2, %0;" : "+l"(acc2) : "l"(Xb.x), "l"(gg));
        asm("fma.rn.f32x2 %0, %1, %2, %0;" : "+l"(acc3) : "l"(Xb.y), "l"(gg));
    }

    // write partials (deterministic two-pass reduction, no atomics)
    ulonglong2* pp = reinterpret_cast<ulonglong2*>(&g_part[blockIdx.y][j][0]);
    pp[0] = make_ulonglong2(acc0, acc1);
    pp[1] = make_ulonglong2(acc2, acc3);
}

// -------- reduce + epilogue: sum chunks, apply power/bias, elu --------
__global__ void reduce_kernel(const float* __restrict__ power,
                              const float* __restrict__ bias,
                              float* __restrict__ out) {
    int j = blockIdx.x * blockDim.x + threadIdx.x;
    if (j >= N) return;
    float s0 = 0.f, s1 = 0.f, s2 = 0.f, s3 = 0.f;
    float s4 = 0.f, s5 = 0.f, s6 = 0.f, s7 = 0.f;
    #pragma unroll
    for (int c = 0; c < NCHUNK; c++) {
        float4 a = g_part[c][j][0];
        float4 b = g_part[c][j][1];
        s0 += a.x; s1 += a.y; s2 += a.z; s3 += a.w;
        s4 += b.x; s5 += b.y; s6 += b.z; s7 += b.w;
    }
    float pw = power[j] * INV_D2;
    float bi = bias[j];
    float v;
    v = fmaf(s0, pw, -bi); out[0 * N + j] = v > 0.f ? v : expm1f(v);
    v = fmaf(s1, pw, -bi); out[1 * N + j] = v > 0.f ? v : expm1f(v);
    v = fmaf(s2, pw, -bi); out[2 * N + j] = v > 0.f ? v : expm1f(v);
    v = fmaf(s3, pw, -bi); out[3 * N + j] = v > 0.f ? v : expm1f(v);
    v = fmaf(s4, pw, -bi); out[4 * N + j] = v > 0.f ? v : expm1f(v);
    v = fmaf(s5, pw, -bi); out[5 * N + j] = v > 0.f ? v : expm1f(v);
    v = fmaf(s6, pw, -bi); out[6 * N + j] = v > 0.f ? v : expm1f(v);
    v = fmaf(s7, pw, -bi); out[7 * N + j] = v > 0.f ? v : expm1f(v);
}

extern "C" void kernel_launch(void* const* d_in, const int* in_sizes, int n_in,
                              void* d_out, int out_size) {
    const float* x      = (const float*)d_in[0];
    const float* pos    = (const float*)d_in[1];
    const float* indir  = (const float*)d_in[2];
    const float* outdir = (const float*)d_in[3];
    const float* power  = (const float*)d_in[4];
    const float* bias   = (const float*)d_in[5];
    float* out = (float*)d_out;

    prep_kernel<<<N / 256, 256>>>(x, pos, indir, outdir);
    dim3 grid(NJT, NCHUNK);
    main_kernel<<<grid, JT>>>();
    reduce_kernel<<<N / 256, 256>>>(power, bias, out);
}

// round 6
// speedup vs baseline: 1.1835x; 1.1835x over previous
#include <cuda_runtime.h>

#define N 4096
#define B 8
#define JT 128             // j per block == threads per block
#define ICH 128            // i per chunk
#define NCHUNK (N / ICH)   // 32
#define NJT (N / JT)       // 32

#define LOG2E 1.4426950408889634f
#define EXP_NEG1 0.36787944117144233f
// D = e - e^-1 ; fold 1/D^2 into the power scaling at the epilogue
#define DVAL 2.3504023872876028f
#define INV_D2 (1.0f / (DVAL * DVAL))
#define EPS 1e-5f

typedef unsigned long long ull;

// -------- packed f32x2 helpers --------
__device__ __forceinline__ ull pk(float lo, float hi) {
    ull r; asm("mov.b64 %0, {%1, %2};" : "=l"(r) : "f"(lo), "f"(hi)); return r;
}
__device__ __forceinline__ void upk(ull v, float& lo, float& hi) {
    asm("mov.b64 {%0, %1}, %2;" : "=f"(lo), "=f"(hi) : "l"(v));
}
__device__ __forceinline__ ull padd(ull a, ull b) {
    ull r; asm("add.rn.f32x2 %0, %1, %2;" : "=l"(r) : "l"(a), "l"(b)); return r;
}
__device__ __forceinline__ ull pmul(ull a, ull b) {
    ull r; asm("mul.rn.f32x2 %0, %1, %2;" : "=l"(r) : "l"(a), "l"(b)); return r;
}
__device__ __forceinline__ ull pfma(ull a, ull b, ull c) {
    ull r; asm("fma.rn.f32x2 %0, %1, %2, %3;" : "=l"(r) : "l"(a), "l"(b), "l"(c)); return r;
}
__device__ __forceinline__ float rsqrt_ap(float v) {
    float r; asm("rsqrt.approx.f32 %0, %1;" : "=f"(r) : "f"(v)); return r;
}
__device__ __forceinline__ float ex2_ap(float v) {
    float r; asm("ex2.approx.ftz.f32 %0, %1;" : "=f"(r) : "f"(v)); return r;
}

// -------- device scratch (no allocations allowed) --------
// partial sums: [chunk][j] -> 8 batch floats as 2 float4
__device__ float4 g_part[NCHUNK][N][2];
// per-j-tile arrival counters (zero-initialized; reset by reducing block)
__device__ int g_cnt[NJT];

// -------- single fused kernel --------
__global__ void __launch_bounds__(JT) fused_kernel(const float* __restrict__ x,
                                                   const float* __restrict__ pos,
                                                   const float* __restrict__ indir,
                                                   const float* __restrict__ outdir,
                                                   const float* __restrict__ power,
                                                   const float* __restrict__ bias,
                                                   float* __restrict__ out) {
    // i-side geometry, pair-SoA: per pair p (i=2p,2p+1):
    // [-px0,-px1, -py0,-py1, -pz0,-pz1, ox0,ox1, oy0,oy1, oz0,oz1]  (12 floats, 48B, 16B-aligned)
    __shared__ float sG[(ICH / 2) * 12];             // 3 KB
    __shared__ float sXf[ICH * 8];                   // xT tile: sXf[i*8+b], 4 KB
    __shared__ int s_last;

    const int tid   = threadIdx.x;
    const int jtile = blockIdx.x;
    const int chunk = blockIdx.y;
    const int i0    = chunk * ICH;
    const int j     = jtile * JT + tid;

    // ---- stage i-chunk (one i per thread), fused prep ----
    {
        const int i = i0 + tid;
        const int p = tid >> 1, h = tid & 1;
        float* gp_ = sG + p * 12;
        gp_[0  + h] = -pos[3 * i + 0];
        gp_[2  + h] = -pos[3 * i + 1];
        gp_[4  + h] = -pos[3 * i + 2];
        gp_[6  + h] = outdir[3 * i + 0] * LOG2E;
        gp_[8  + h] = outdir[3 * i + 1] * LOG2E;
        gp_[10 + h] = outdir[3 * i + 2] * LOG2E;
        #pragma unroll
        for (int b = 0; b < B; b++)
            sXf[tid * 8 + b] = x[b * N + i];
    }

    // ---- j-side registers (packed broadcasts) ----
    const ull pjx2 = pk(pos[3 * j + 0], pos[3 * j + 0]);
    const ull pjy2 = pk(pos[3 * j + 1], pos[3 * j + 1]);
    const ull pjz2 = pk(pos[3 * j + 2], pos[3 * j + 2]);
    const float inx = indir[3 * j + 0] * LOG2E;
    const float iny = indir[3 * j + 1] * LOG2E;
    const float inz = indir[3 * j + 2] * LOG2E;
    const ull inx2 = pk(inx, inx), iny2 = pk(iny, iny), inz2 = pk(inz, inz);
    const ull cneg = pk(-EXP_NEG1, -EXP_NEG1);

    __syncthreads();

    ull acc0 = 0ull, acc1 = 0ull, acc2 = 0ull, acc3 = 0ull;

    #pragma unroll 4
    for (int p = 0; p < ICH / 2; p++) {
        const ulonglong2* gq = reinterpret_cast<const ulonglong2*>(sG + p * 12);
        ulonglong2 q0 = gq[0];   // -posx pair | -posy pair
        ulonglong2 q1 = gq[1];   // -posz pair |  odx pair
        ulonglong2 q2 = gq[2];   //  ody pair  |  odz pair

        ull dxp = padd(pjx2, q0.x);
        ull dyp = padd(pjy2, q0.y);
        ull dzp = padd(pjz2, q1.x);

        ull d2p = pfma(dxp, dxp, pfma(dyp, dyp, pmul(dzp, dzp)));
        ull dap = pfma(dxp, q1.y, pfma(dyp, q2.x, pmul(dzp, q2.y)));   // delta . outdirL_i
        ull dbp = pfma(dxp, inx2, pfma(dyp, iny2, pmul(dzp, inz2)));   // delta . indirL_j

        float d20, d21; upk(d2p, d20, d21);
        float r0 = rsqrt_ap(fmaxf(d20, EPS));
        float r1 = rsqrt_ap(fmaxf(d21, EPS));
        ull rp = pk(r0, r1);

        ull ap = pmul(dap, rp);
        ull bp = pmul(dbp, rp);
        float a0, a1, b0, b1;
        upk(ap, a0, a1); upk(bp, b0, b1);

        ull eap = pk(ex2_ap(a0), ex2_ap(a1));
        ull ebp = pk(ex2_ap(b0), ex2_ap(b1));

        ull gp2 = pmul(padd(eap, cneg), padd(ebp, cneg));   // unnormalized gate pair
        float g0, g1; upk(gp2, g0, g1);
        ull gg0 = pk(g0, g0);
        ull gg1 = pk(g1, g1);

        const ulonglong2* X0 = reinterpret_cast<const ulonglong2*>(sXf + (2 * p) * 8);
        ulonglong2 Xa = X0[0], Xb = X0[1];   // i = 2p : b0..3 | b4..7
        ulonglong2 Xc = X0[2], Xd = X0[3];   // i = 2p+1

        acc0 = pfma(Xa.x, gg0, acc0);
        acc1 = pfma(Xa.y, gg0, acc1);
        acc2 = pfma(Xb.x, gg0, acc2);
        acc3 = pfma(Xb.y, gg0, acc3);
        acc0 = pfma(Xc.x, gg1, acc0);
        acc1 = pfma(Xc.y, gg1, acc1);
        acc2 = pfma(Xd.x, gg1, acc2);
        acc3 = pfma(Xd.y, gg1, acc3);
    }

    // ---- write partials ----
    ulonglong2* pp = reinterpret_cast<ulonglong2*>(&g_part[chunk][j][0]);
    pp[0] = make_ulonglong2(acc0, acc1);
    pp[1] = make_ulonglong2(acc2, acc3);

    // ---- last-block-per-column reduction + epilogue ----
    __threadfence();
    __syncthreads();
    if (tid == 0)
        s_last = (atomicAdd(&g_cnt[jtile], 1) == NCHUNK - 1);
    __syncthreads();

    if (s_last) {
        float s0 = 0.f, s1 = 0.f, s2 = 0.f, s3 = 0.f;
        float s4 = 0.f, s5 = 0.f, s6 = 0.f, s7 = 0.f;
        #pragma unroll
        for (int c = 0; c < NCHUNK; c++) {
            float4 a = __ldcg(&g_part[c][j][0]);
            float4 b = __ldcg(&g_part[c][j][1]);
            s0 += a.x; s1 += a.y; s2 += a.z; s3 += a.w;
            s4 += b.x; s5 += b.y; s6 += b.z; s7 += b.w;
        }
        float pw = power[j] * INV_D2;
        float bi = bias[j];
        float v;
        v = fmaf(s0, pw, -bi); out[0 * N + j] = v > 0.f ? v : expm1f(v);
        v = fmaf(s1, pw, -bi); out[1 * N + j] = v > 0.f ? v : expm1f(v);
        v = fmaf(s2, pw, -bi); out[2 * N + j] = v > 0.f ? v : expm1f(v);
        v = fmaf(s3, pw, -bi); out[3 * N + j] = v > 0.f ? v : expm1f(v);
        v = fmaf(s4, pw, -bi); out[4 * N + j] = v > 0.f ? v : expm1f(v);
        v = fmaf(s5, pw, -bi); out[5 * N + j] = v > 0.f ? v : expm1f(v);
        v = fmaf(s6, pw, -bi); out[6 * N + j] = v > 0.f ? v : expm1f(v);
        v = fmaf(s7, pw, -bi); out[7 * N + j] = v > 0.f ? v : expm1f(v);
        if (tid == 0) g_cnt[jtile] = 0;   // reset for next graph replay
    }
}

extern "C" void kernel_launch(void* const* d_in, const int* in_sizes, int n_in,
                              void* d_out, int out_size) {
    const float* x      = (const float*)d_in[0];
    const float* pos    = (const float*)d_in[1];
    const float* indir  = (const float*)d_in[2];
    const float* outdir = (const float*)d_in[3];
    const float* power  = (const float*)d_in[4];
    const float* bias   = (const float*)d_in[5];
    float* out = (float*)d_out;

    dim3 grid(NJT, NCHUNK);
    fused_kernel<<<grid, JT>>>(x, pos, indir, outdir, power, bias, out);
}